// round 13
// baseline (speedup 1.0000x reference)
#include <cuda_runtime.h>
#include <cuda_bf16.h>
#include <cuda_fp16.h>
#include <cstdint>

// Problem constants
#define B_   4
#define C_   256
#define DQK_ 32
#define N_   4096   // 64*64

typedef uint32_t u32;

// ---------------- scratch (no allocation allowed -> device globals) ----------
__device__ __half        g_q[(size_t)B_ * N_ * DQK_];   // [B][N][32], Q pre-scaled by log2(e)
__device__ __half        g_k[(size_t)B_ * N_ * DQK_];   // [B][N][32]
__device__ __half        g_v[(size_t)B_ * C_ * N_];     // [B][C][N] channel-major
__device__ __nv_bfloat16 g_xT[(size_t)B_ * N_ * C_];    // [B][N][C]  x transposed, bf16
__device__ __nv_bfloat16 g_wcat[320 * 256];             // [Wq*log2e; Wk; Wv]
__device__ float         g_bcat[320];                   // [bq*log2e; bk; bv]

// ---------------- helpers ------------------------------------------------------
__device__ __forceinline__ u32 pack_bf16x2(float lo, float hi) {
    u32 d;
    asm("cvt.rn.bf16x2.f32 %0, %1, %2;" : "=r"(d) : "f"(hi), "f"(lo));
    return d;
}
__device__ __forceinline__ u32 pack_f16x2(float lo, float hi) {
    u32 d;
    asm("cvt.rn.f16x2.f32 %0, %1, %2;" : "=r"(d) : "f"(hi), "f"(lo));
    return d;
}
__device__ __forceinline__ u32 smem_u32(const void* p) {
    u32 a;
    asm("{ .reg .u64 t; cvta.to.shared.u64 t, %1; cvt.u32.u64 %0, t; }" : "=r"(a) : "l"(p));
    return a;
}
__device__ __forceinline__ void sts32(u32 addr, u32 v) {
    asm volatile("st.shared.b32 [%0], %1;" :: "r"(addr), "r"(v) : "memory");
}
__device__ __forceinline__ void ldm_x4(u32 addr, u32& r0, u32& r1, u32& r2, u32& r3) {
    asm volatile("ldmatrix.sync.aligned.m8n8.x4.shared.b16 {%0,%1,%2,%3}, [%4];"
                 : "=r"(r0), "=r"(r1), "=r"(r2), "=r"(r3) : "r"(addr));
}
// bf16 inputs, f32 accum (projection GEMM)
__device__ __forceinline__ void mma_bf16(float* d, const u32* a, const u32* b) {
    asm volatile(
        "mma.sync.aligned.m16n8k16.row.col.f32.bf16.bf16.f32 "
        "{%0,%1,%2,%3},{%4,%5,%6,%7},{%8,%9},{%0,%1,%2,%3};"
        : "+f"(d[0]), "+f"(d[1]), "+f"(d[2]), "+f"(d[3])
        : "r"(a[0]), "r"(a[1]), "r"(a[2]), "r"(a[3]), "r"(b[0]), "r"(b[1]));
}
// fp16 inputs, f32 accum (S = K.Q^T)
__device__ __forceinline__ void mma_f16_f32(float* d, const u32* a, const u32* b) {
    asm volatile(
        "mma.sync.aligned.m16n8k16.row.col.f32.f16.f16.f32 "
        "{%0,%1,%2,%3},{%4,%5,%6,%7},{%8,%9},{%0,%1,%2,%3};"
        : "+f"(d[0]), "+f"(d[1]), "+f"(d[2]), "+f"(d[3])
        : "r"(a[0]), "r"(a[1]), "r"(a[2]), "r"(a[3]), "r"(b[0]), "r"(b[1]));
}
// fp16 inputs, fp16 accum (PV) — D is 2 regs (4 halves)
__device__ __forceinline__ void mma_f16(u32* d, const u32* a, const u32* b) {
    asm volatile(
        "mma.sync.aligned.m16n8k16.row.col.f16.f16.f16.f16 "
        "{%0,%1},{%2,%3,%4,%5},{%6,%7},{%0,%1};"
        : "+r"(d[0]), "+r"(d[1])
        : "r"(a[0]), "r"(a[1]), "r"(a[2]), "r"(a[3]), "r"(b[0]), "r"(b[1]));
}
__device__ __forceinline__ void cpa16(u32 dst, const void* src) {
    asm volatile("cp.async.cg.shared.global [%0], [%1], 16;" :: "r"(dst), "l"(src));
}
#define CP_COMMIT  asm volatile("cp.async.commit_group;")
#define CP_WAIT0   asm volatile("cp.async.wait_group 0;")
#define CP_WAIT1   asm volatile("cp.async.wait_group 1;")

__device__ __forceinline__ u32 swz(u32 off) { return off ^ ((off >> 3) & 0x70); }

#define L2E 1.44269504088896f

// =============================================================================
// Kernel 0a: weight stack + bf16 convert. grid(320), block(256).
// =============================================================================
__global__ void wconv(const float* __restrict__ Wq, const float* __restrict__ bq,
                      const float* __restrict__ Wk, const float* __restrict__ bk,
                      const float* __restrict__ Wv, const float* __restrict__ bv)
{
    int j = blockIdx.x, c = threadIdx.x;
    const float* src;
    float s = 1.0f, bias;
    if (j < 32)       { src = Wq + j * 256;        s = L2E; bias = bq[j] * L2E; }
    else if (j < 64)  { src = Wk + (j - 32) * 256;          bias = bk[j - 32];  }
    else              { src = Wv + (j - 64) * 256;          bias = bv[j - 64];  }
    g_wcat[j * 256 + c] = __float2bfloat16(src[c] * s);
    if (c == 0) g_bcat[j] = bias;
}

// =============================================================================
// Kernel 0b: x [B][C][N] f32 -> g_xT [B][N][C] bf16. grid(64,4,4), block(256).
// =============================================================================
__global__ __launch_bounds__(256) void xT_kernel(const float* __restrict__ x)
{
    __shared__ float T[64][65];
    const int tid = threadIdx.x;
    const int n0 = blockIdx.x * 64, c0 = blockIdx.y * 64, b = blockIdx.z;

    {
        int cr = tid >> 2, q = tid & 3;
        const float4* src = (const float4*)(x + ((size_t)(b * C_ + c0 + cr)) * N_ + n0 + q * 16);
#pragma unroll
        for (int i = 0; i < 4; ++i) {
            float4 v = src[i];
            int nn = q * 16 + i * 4;
            T[cr][nn] = v.x; T[cr][nn + 1] = v.y; T[cr][nn + 2] = v.z; T[cr][nn + 3] = v.w;
        }
    }
    __syncthreads();

    u32* dst = (u32*)g_xT;
#pragma unroll
    for (int i = 0; i < 8; ++i) {
        int idx = tid * 8 + i;
        int n = idx >> 5, cp = idx & 31;
        u32 v = pack_bf16x2(T[2 * cp][n], T[2 * cp + 1][n]);
        dst[((size_t)(b * N_ + n0 + n)) * 128 + (c0 >> 1) + cp] = v;
    }
}

// =============================================================================
// Kernel 1: projection GEMM on tensor cores. Outputs fp16 Q/K/V.
// =============================================================================
#define WT_OFF 1024
#define XT_OFF 17408
#define SMEM_P 50176

__global__ __launch_bounds__(128, 4)
void proj_gemm()
{
    extern __shared__ char sm[];
    const u32 sb = smem_u32(sm);
    float* bs = (float*)sm;
    const int tid = threadIdx.x;
    const int w = tid >> 5, lane = tid & 31;
    const int gid = lane >> 2, qid = lane & 3;
    const int n0 = blockIdx.x * 128;
    const int z  = blockIdx.y;
    const int b  = blockIdx.z;
    const bool qk = (z == 0);
    const int jbase = qk ? 0 : z * 64;

    if (tid < 64) bs[tid] = g_bcat[jbase + tid];

    auto load_chunk = [&](int kc) {
        int buf = kc & 1;
#pragma unroll
        for (int i = 0; i < 4; ++i) {
            int idx = i * 128 + tid;
            int r = idx >> 3, q = idx & 7;
            cpa16(sb + WT_OFF + buf * 8192 + swz(r * 128 + q * 16),
                  g_wcat + (size_t)(jbase + r) * 256 + kc * 64 + q * 8);
        }
#pragma unroll
        for (int i = 0; i < 8; ++i) {
            int idx = i * 128 + tid;
            int r = idx >> 3, q = idx & 7;
            cpa16(sb + XT_OFF + buf * 16384 + swz(r * 128 + q * 16),
                  g_xT + ((size_t)(b * N_) + n0 + r) * 256 + kc * 64 + q * 8);
        }
    };

    load_chunk(0);
    CP_COMMIT;

    float D[2][8][4];
#pragma unroll
    for (int mt = 0; mt < 2; ++mt)
#pragma unroll
        for (int nt = 0; nt < 8; ++nt)
#pragma unroll
            for (int r = 0; r < 4; ++r) D[mt][nt][r] = 0.0f;

    for (int kc = 0; kc < 4; ++kc) {
        if (kc < 3) { load_chunk(kc + 1); CP_COMMIT; CP_WAIT1; }
        else        { CP_WAIT0; }
        __syncthreads();

        const u32 wbase = sb + WT_OFF + (kc & 1) * 8192;
        const u32 xbase = sb + XT_OFF + (kc & 1) * 16384;
        const u32 abase = qk ? xbase : wbase;
        const u32 bbase = qk ? wbase : xbase;
        const int arow  = qk ? w * 32 : (w & 1) * 32;
        const int brow  = qk ? 0 : (w >> 1) * 64;

#pragma unroll
        for (int ks = 0; ks < 4; ++ks) {
            u32 aA[2][4];
#pragma unroll
            for (int mt = 0; mt < 2; ++mt) {
                int row = arow + mt * 16 + (lane & 15);
                ldm_x4(abase + swz(row * 128 + (lane >> 4) * 16 + ks * 32),
                       aA[mt][0], aA[mt][1], aA[mt][2], aA[mt][3]);
            }
#pragma unroll
            for (int ntp = 0; ntp < 4; ++ntp) {
                u32 bB[4];
                int nrow = brow + ntp * 16 + (lane & 7) + ((lane >> 4) & 1) * 8;
                ldm_x4(bbase + swz(nrow * 128 + ((lane >> 3) & 1) * 16 + ks * 32),
                       bB[0], bB[1], bB[2], bB[3]);
                mma_bf16(D[0][2 * ntp],     aA[0], bB);
                mma_bf16(D[0][2 * ntp + 1], aA[0], bB + 2);
                mma_bf16(D[1][2 * ntp],     aA[1], bB);
                mma_bf16(D[1][2 * ntp + 1], aA[1], bB + 2);
            }
        }
        __syncthreads();
    }

    if (qk) {
#pragma unroll
        for (int mt = 0; mt < 2; ++mt) {
            int n = n0 + w * 32 + mt * 16 + gid;
#pragma unroll
            for (int nt = 0; nt < 8; ++nt) {
                int j = nt * 8 + 2 * qid;
                float b0 = bs[j], b1 = bs[j + 1];
                u32 lo = pack_f16x2(D[mt][nt][0] + b0, D[mt][nt][1] + b1);
                u32 hi = pack_f16x2(D[mt][nt][2] + b0, D[mt][nt][3] + b1);
                int jj = j < 32 ? j : j - 32;
                u32* dst = (u32*)(j < 32 ? g_q : g_k);
                dst[((size_t)(b * N_) + n) * 16 + (jj >> 1)]       = lo;
                dst[((size_t)(b * N_) + n + 8) * 16 + (jj >> 1)]   = hi;
            }
        }
    } else {
#pragma unroll
        for (int mt = 0; mt < 2; ++mt) {
            int chl = (w & 1) * 32 + mt * 16 + gid;
            int ch  = (z - 1) * 64 + chl;
            float bv0 = bs[chl], bv1 = bs[chl + 8];
#pragma unroll
            for (int nt = 0; nt < 8; ++nt) {
                int pix = (w >> 1) * 64 + nt * 8 + 2 * qid;
                u32 lo = pack_f16x2(D[mt][nt][0] + bv0, D[mt][nt][1] + bv0);
                u32 hi = pack_f16x2(D[mt][nt][2] + bv1, D[mt][nt][3] + bv1);
                u32* dst = (u32*)g_v;
                dst[((size_t)(b * C_ + ch)) * 2048 + ((n0 + pix) >> 1)]     = lo;
                dst[((size_t)(b * C_ + ch + 8)) * 2048 + ((n0 + pix) >> 1)] = hi;
            }
        }
    }
}

// =============================================================================
// Kernel 2: fp16 flash attention — 512 threads, BLOCK_M=128, 1 CTA/SM.
// R10 pipeline (1 barrier/tile, plain loop, incremental u32 buffer offsets)
// with K-SPLIT PV: each PV warp owns a 64x64 output tile over HALF the
// k-range (kh = wid>>3); warp pairs reduce partials in the epilogue stage.
// LDS reads/tile drop 1920 -> 1408 wavefronts.
// SMEM: rowsum[128]f @0 | K 16KB @1024 | Q 2x8KB @17408 | P 2x16KB @33792 |
//       V 3x32KB @66560  => 164864 B
// =============================================================================
#define K_OFF     1024
#define Q_OFF     17408
#define P_OFF     33792
#define V_OFF     66560
#define SMEM_F    164864
#define STAGE_OFF 1024
#define NT        64

__device__ __forceinline__ void load_qv(u32 sb, int tid, int b, int t,
                                        u32 qoff, u32 voff) {
    const int n0 = t * 64;
    if (tid < 256) {   // Q: 64 rows x 32 f16
        int row = tid >> 2, ch = tid & 3;
        cpa16(sb + Q_OFF + qoff + swz(row * 128 + ch * 16),
              g_q + (size_t)(b * N_ + n0 + row) * DQK_ + ch * 8);
    }
    // V: 256 channel rows x 64 f16 = 2048 cpa16 over 512 threads
    const __half* vbase = g_v + (size_t)b * C_ * N_ + n0;
#pragma unroll
    for (int r = 0; r < 4; ++r) {
        int idx = tid + 512 * r;
        int c = idx >> 3, ch = idx & 7;
        cpa16(sb + V_OFF + voff + swz(c * 128 + ch * 16),
              vbase + (size_t)c * N_ + ch * 8);
    }
}

__global__ __launch_bounds__(512, 1)
void flash_mma(const float* __restrict__ x,
               const float* __restrict__ gamma,
               float* __restrict__ out)
{
    extern __shared__ char sm[];
    const u32 sb = smem_u32(sm);
    const int tid  = threadIdx.x;
    const int wid  = tid >> 5;
    const int lane = tid & 31;
    const int gid  = lane >> 2;
    const int qid  = lane & 3;
    const int b    = blockIdx.y;
    const int m0   = blockIdx.x * 128;

    if (tid < 128) ((float*)sm)[tid] = 0.0f;

    // prologue: K tile + tile 0
    {
        int row = tid >> 2, ch = tid & 3;
        cpa16(sb + K_OFF + swz(row * 128 + ch * 16),
              g_k + (size_t)(b * N_ + m0 + row) * DQK_ + ch * 8);
    }
    load_qv(sb, tid, b, 0, 0u, 0u);
    CP_COMMIT;
    CP_WAIT0;
    __syncthreads();

    // persistent K A-frags: rows (wid&7)*16 .. +15
    u32 aK[2][4];
    {
        int row = (wid & 7) * 16 + (lane & 15);
#pragma unroll
        for (int ks = 0; ks < 2; ++ks) {
            u32 addr = sb + K_OFF + swz(row * 128 + (lane >> 4) * 16 + ks * 32);
            ldm_x4(addr, aK[ks][0], aK[ks][1], aK[ks][2], aK[ks][3]);
        }
    }

    u32 D[4][8][2];                // fp16x2 accumulators, 64 regs (k-split)
#pragma unroll
    for (int ms = 0; ms < 4; ++ms)
#pragma unroll
        for (int cg = 0; cg < 8; ++cg) { D[ms][cg][0] = 0u; D[ms][cg][1] = 0u; }
    float rs0 = 0.0f, rs1 = 0.0f;

    const int rg  = wid & 7;         // S row group
    const int csh = wid >> 3;        // S col half
    const int pr  = wid & 1;         // PV row half (64 rows)
    const int pc  = (wid >> 1) & 3;  // PV channel quarter (64 ch)
    const int kh  = wid >> 3;        // PV k half (32 of 64 n)

    // hoisted lane-invariant address pieces
    const int s_nbase  = csh * 32 + (lane & 7) + ((lane >> 4) & 1) * 8;
    const int s_nhalf  = ((lane >> 3) & 1) * 16;
    const int pv_prow  = pr * 64 + (lane & 15);
    const int pv_pbyte = (lane >> 4) * 16 + kh * 64;        // + ksn*32
    const int pv_crow  = pc * 64 + (lane & 7) + ((lane >> 4) & 1) * 8;
    const int pv_cbyte = ((lane >> 3) & 1) * 16 + kh * 64;  // + ksn*32

    // PV over P/V buffers at given u32 offsets (k-split: 2 ksn steps)
    auto pv_step = [&](u32 pb, u32 vb) {
#pragma unroll
        for (int ksn = 0; ksn < 2; ++ksn) {
            u32 aP[4][4];
#pragma unroll
            for (int ms = 0; ms < 4; ++ms) {
                ldm_x4(pb + swz((u32)((pv_prow + ms * 16) * 128 + pv_pbyte + ksn * 32)),
                       aP[ms][0], aP[ms][1], aP[ms][2], aP[ms][3]);
            }
            u32 bV[4][4];
#pragma unroll
            for (int pp = 0; pp < 4; ++pp) {
                ldm_x4(vb + swz((u32)((pv_crow + pp * 16) * 128 + pv_cbyte + ksn * 32)),
                       bV[pp][0], bV[pp][1], bV[pp][2], bV[pp][3]);
            }
#pragma unroll
            for (int ms = 0; ms < 4; ++ms)
#pragma unroll
                for (int cg = 0; cg < 8; ++cg)
                    mma_f16(D[ms][cg], aP[ms], &bV[cg >> 1][(cg & 1) * 2]);
        }
    };

    u32 q_cur = 0, v_cur = 0, v_prev = 0, p_cur = 0;

    for (int t = 0; t < NT; ++t) {
        CP_WAIT0;                    // QV(t) arrived (committed one tile ago)
        __syncthreads();             // QV(t) + P(t-1) visible

        // ---- prefetch tile t+1 (clamped tail reload is idempotent) ----
        {
            u32 q_nxt = q_cur ^ 8192u;
            u32 v_nxt = (v_cur == 65536u) ? 0u : v_cur + 32768u;
            int tn = (t + 1 < NT) ? t + 1 : NT - 1;
            load_qv(sb, tid, b, tn, q_nxt, v_nxt);
            CP_COMMIT;
        }

        // ---- S(t) = K . Q(t)^T ----
        const u32 qb = sb + Q_OFF + q_cur;
        float S[4][4];
#pragma unroll
        for (int ns = 0; ns < 4; ++ns)
#pragma unroll
            for (int r = 0; r < 4; ++r) S[ns][r] = 0.0f;

        u32 bQ[2][2][4];
#pragma unroll
        for (int nn = 0; nn < 2; ++nn) {
            int nrow = s_nbase + nn * 16;
#pragma unroll
            for (int ks = 0; ks < 2; ++ks) {
                u32 addr = qb + swz((u32)(nrow * 128 + s_nhalf + ks * 32));
                ldm_x4(addr, bQ[ks][nn][0], bQ[ks][nn][1], bQ[ks][nn][2], bQ[ks][nn][3]);
            }
        }
#pragma unroll
        for (int ns = 0; ns < 4; ++ns)
#pragma unroll
            for (int ks = 0; ks < 2; ++ks)
                mma_f16_f32(S[ns], aK[ks], &bQ[ks][ns >> 1][(ns & 1) * 2]);

        // ---- PV(t-1): D += P(t-1) . V(t-1) (k-split) ----
        if (t > 0) pv_step(sb + P_OFF + (p_cur ^ 16384u), sb + V_OFF + v_prev);

        // ---- exp(t) -> P(p_cur); rowsums in f16x2, flushed to f32 ----
        {
            const int mlo = rg * 16 + gid;
            const u32 pw = sb + P_OFF + p_cur;
            u32 rsa = 0u, rsb = 0u;
#pragma unroll
            for (int ns = 0; ns < 4; ++ns) {
                u32 p0 = pack_f16x2(S[ns][0], S[ns][1]);
                u32 p1 = pack_f16x2(S[ns][2], S[ns][3]);
                asm("ex2.approx.f16x2 %0, %0;" : "+r"(p0));
                asm("ex2.approx.f16x2 %0, %0;" : "+r"(p1));
                asm("add.rn.f16x2 %0, %0, %1;" : "+r"(rsa) : "r"(p0));
                asm("add.rn.f16x2 %0, %0, %1;" : "+r"(rsb) : "r"(p1));
                int n = csh * 32 + ns * 8 + 2 * qid;
                sts32(pw + swz((u32)(mlo * 128 + n * 2)), p0);
                sts32(pw + swz((u32)((mlo + 8) * 128 + n * 2)), p1);
            }
            float2 fa = __half22float2(*(__half2*)&rsa);
            float2 fb = __half22float2(*(__half2*)&rsb);
            rs0 += fa.x + fa.y;
            rs1 += fb.x + fb.y;
        }

        // rotate buffers
        v_prev = v_cur;
        v_cur  = (v_cur == 65536u) ? 0u : v_cur + 32768u;
        q_cur ^= 8192u;
        p_cur ^= 16384u;
    }

    // ---- tail PV(NT-1): P buffer = p_cur^16384 (last written), V = v_prev ----
    CP_WAIT0;
    __syncthreads();
    pv_step(sb + P_OFF + (p_cur ^ 16384u), sb + V_OFF + v_prev);

    // ---- row sums: 4-lane reduce + cross-warp atomic ----
    __syncthreads();
    rs0 += __shfl_xor_sync(0xffffffffu, rs0, 1);
    rs0 += __shfl_xor_sync(0xffffffffu, rs0, 2);
    rs1 += __shfl_xor_sync(0xffffffffu, rs1, 1);
    rs1 += __shfl_xor_sync(0xffffffffu, rs1, 2);
    if (qid == 0) {
        atomicAdd(&((float*)sm)[rg * 16 + gid],     rs0);
        atomicAdd(&((float*)sm)[rg * 16 + gid + 8], rs1);
    }
    __syncthreads();

    // ---- epilogue: two 64-row passes; k-split partials reduced in stage ----
    float* stage = (float*)(sm + STAGE_OFF);   // [256][66] f32
    const float g = gamma[0];
#pragma unroll
    for (int h = 0; h < 2; ++h) {
        // pass 1: kh==0 partial writes
        if (pr == h && kh == 0) {
#pragma unroll
            for (int ms = 0; ms < 4; ++ms) {
                int l0 = ms * 16 + gid, l1 = l0 + 8;
                float i0 = 1.0f / ((float*)sm)[h * 64 + l0];
                float i1 = 1.0f / ((float*)sm)[h * 64 + l1];
#pragma unroll
                for (int cg = 0; cg < 8; ++cg) {
                    int c = pc * 64 + cg * 8 + 2 * qid;
                    float2 flo = __half22float2(*reinterpret_cast<__half2*>(&D[ms][cg][0]));
                    float2 fhi = __half22float2(*reinterpret_cast<__half2*>(&D[ms][cg][1]));
                    stage[c * 66 + l0]       = flo.x * i0;
                    stage[(c + 1) * 66 + l0] = flo.y * i0;
                    stage[c * 66 + l1]       = fhi.x * i1;
                    stage[(c + 1) * 66 + l1] = fhi.y * i1;
                }
            }
        }
        __syncthreads();
        // pass 2: kh==1 partial adds
        if (pr == h && kh == 1) {
#pragma unroll
            for (int ms = 0; ms < 4; ++ms) {
                int l0 = ms * 16 + gid, l1 = l0 + 8;
                float i0 = 1.0f / ((float*)sm)[h * 64 + l0];
                float i1 = 1.0f / ((float*)sm)[h * 64 + l1];
#pragma unroll
                for (int cg = 0; cg < 8; ++cg) {
                    int c = pc * 64 + cg * 8 + 2 * qid;
                    float2 flo = __half22float2(*reinterpret_cast<__half2*>(&D[ms][cg][0]));
                    float2 fhi = __half22float2(*reinterpret_cast<__half2*>(&D[ms][cg][1]));
                    stage[c * 66 + l0]       += flo.x * i0;
                    stage[(c + 1) * 66 + l0] += flo.y * i0;
                    stage[c * 66 + l1]       += fhi.x * i1;
                    stage[(c + 1) * 66 + l1] += fhi.y * i1;
                }
            }
        }
        __syncthreads();

#pragma unroll 4
        for (int i = 0; i < 32; ++i) {
            int m = tid & 63;
            int c = (tid >> 6) + 8 * i;
            size_t ga = ((size_t)(b * C_ + c)) * N_ + m0 + h * 64 + m;
            out[ga] = g * stage[c * 66 + m] + x[ga];
        }
        __syncthreads();
    }
}

// =============================================================================
// launcher
// =============================================================================
extern "C" void kernel_launch(void* const* d_in, const int* in_sizes, int n_in,
                              void* d_out, int out_size)
{
    const float* x     = (const float*)d_in[0];
    const float* Wq    = (const float*)d_in[1];
    const float* bq    = (const float*)d_in[2];
    const float* Wk    = (const float*)d_in[3];
    const float* bk    = (const float*)d_in[4];
    const float* Wv    = (const float*)d_in[5];
    const float* bv    = (const float*)d_in[6];
    const float* gamma = (const float*)d_in[7];
    float* out = (float*)d_out;

    (void)cudaFuncSetAttribute(proj_gemm,
                               cudaFuncAttributeMaxDynamicSharedMemorySize, SMEM_P);
    (void)cudaFuncSetAttribute(flash_mma,
                               cudaFuncAttributeMaxDynamicSharedMemorySize, SMEM_F);

    wconv<<<320, 256>>>(Wq, bq, Wk, bk, Wv, bv);
    xT_kernel<<<dim3(N_ / 64, C_ / 64, B_), 256>>>(x);
    proj_gemm<<<dim3(N_ / 128, 5, B_), 128, SMEM_P>>>();
    flash_mma<<<dim3(N_ / 128, B_), 512, SMEM_F>>>(x, gamma, out);
}

// round 14
// speedup vs baseline: 1.0292x; 1.0292x over previous
#include <cuda_runtime.h>
#include <cuda_bf16.h>
#include <cuda_fp16.h>
#include <cstdint>

// Problem constants
#define B_   4
#define C_   256
#define DQK_ 32
#define N_   4096   // 64*64

typedef uint32_t u32;

// ---------------- scratch (no allocation allowed -> device globals) ----------
__device__ __half        g_q[(size_t)B_ * N_ * DQK_];   // [B][N][32], Q pre-scaled by log2(e)
__device__ __half        g_k[(size_t)B_ * N_ * DQK_];   // [B][N][32]
__device__ __half        g_v[(size_t)B_ * C_ * N_];     // [B][C][N] channel-major
__device__ __nv_bfloat16 g_xT[(size_t)B_ * N_ * C_];    // [B][N][C]  x transposed, bf16
__device__ __nv_bfloat16 g_wcat[320 * 256];             // [Wq*log2e; Wk; Wv]
__device__ float         g_bcat[320];                   // [bq*log2e; bk; bv]

// ---------------- helpers ------------------------------------------------------
__device__ __forceinline__ u32 pack_bf16x2(float lo, float hi) {
    u32 d;
    asm("cvt.rn.bf16x2.f32 %0, %1, %2;" : "=r"(d) : "f"(hi), "f"(lo));
    return d;
}
__device__ __forceinline__ u32 pack_f16x2(float lo, float hi) {
    u32 d;
    asm("cvt.rn.f16x2.f32 %0, %1, %2;" : "=r"(d) : "f"(hi), "f"(lo));
    return d;
}
__device__ __forceinline__ u32 smem_u32(const void* p) {
    u32 a;
    asm("{ .reg .u64 t; cvta.to.shared.u64 t, %1; cvt.u32.u64 %0, t; }" : "=r"(a) : "l"(p));
    return a;
}
__device__ __forceinline__ void sts32(u32 addr, u32 v) {
    asm volatile("st.shared.b32 [%0], %1;" :: "r"(addr), "r"(v) : "memory");
}
__device__ __forceinline__ void ldm_x4(u32 addr, u32& r0, u32& r1, u32& r2, u32& r3) {
    asm volatile("ldmatrix.sync.aligned.m8n8.x4.shared.b16 {%0,%1,%2,%3}, [%4];"
                 : "=r"(r0), "=r"(r1), "=r"(r2), "=r"(r3) : "r"(addr));
}
// bf16 inputs, f32 accum (projection GEMM)
__device__ __forceinline__ void mma_bf16(float* d, const u32* a, const u32* b) {
    asm volatile(
        "mma.sync.aligned.m16n8k16.row.col.f32.bf16.bf16.f32 "
        "{%0,%1,%2,%3},{%4,%5,%6,%7},{%8,%9},{%0,%1,%2,%3};"
        : "+f"(d[0]), "+f"(d[1]), "+f"(d[2]), "+f"(d[3])
        : "r"(a[0]), "r"(a[1]), "r"(a[2]), "r"(a[3]), "r"(b[0]), "r"(b[1]));
}
// fp16 inputs, f32 accum (S = K.Q^T)
__device__ __forceinline__ void mma_f16_f32(float* d, const u32* a, const u32* b) {
    asm volatile(
        "mma.sync.aligned.m16n8k16.row.col.f32.f16.f16.f32 "
        "{%0,%1,%2,%3},{%4,%5,%6,%7},{%8,%9},{%0,%1,%2,%3};"
        : "+f"(d[0]), "+f"(d[1]), "+f"(d[2]), "+f"(d[3])
        : "r"(a[0]), "r"(a[1]), "r"(a[2]), "r"(a[3]), "r"(b[0]), "r"(b[1]));
}
// fp16 inputs, fp16 accum (PV) — D is 2 regs (4 halves)
__device__ __forceinline__ void mma_f16(u32* d, const u32* a, const u32* b) {
    asm volatile(
        "mma.sync.aligned.m16n8k16.row.col.f16.f16.f16.f16 "
        "{%0,%1},{%2,%3,%4,%5},{%6,%7},{%0,%1};"
        : "+r"(d[0]), "+r"(d[1])
        : "r"(a[0]), "r"(a[1]), "r"(a[2]), "r"(a[3]), "r"(b[0]), "r"(b[1]));
}
__device__ __forceinline__ void cpa16(u32 dst, const void* src) {
    asm volatile("cp.async.cg.shared.global [%0], [%1], 16;" :: "r"(dst), "l"(src));
}
#define CP_COMMIT  asm volatile("cp.async.commit_group;")
#define CP_WAIT0   asm volatile("cp.async.wait_group 0;")
#define CP_WAIT1   asm volatile("cp.async.wait_group 1;")

__device__ __forceinline__ u32 swz(u32 off) { return off ^ ((off >> 3) & 0x70); }

#define L2E 1.44269504088896f

// =============================================================================
// Kernel 0a: weight stack + bf16 convert. grid(320), block(256).
// =============================================================================
__global__ void wconv(const float* __restrict__ Wq, const float* __restrict__ bq,
                      const float* __restrict__ Wk, const float* __restrict__ bk,
                      const float* __restrict__ Wv, const float* __restrict__ bv)
{
    int j = blockIdx.x, c = threadIdx.x;
    const float* src;
    float s = 1.0f, bias;
    if (j < 32)       { src = Wq + j * 256;        s = L2E; bias = bq[j] * L2E; }
    else if (j < 64)  { src = Wk + (j - 32) * 256;          bias = bk[j - 32];  }
    else              { src = Wv + (j - 64) * 256;          bias = bv[j - 64];  }
    g_wcat[j * 256 + c] = __float2bfloat16(src[c] * s);
    if (c == 0) g_bcat[j] = bias;
}

// =============================================================================
// Kernel 0b: x [B][C][N] f32 -> g_xT [B][N][C] bf16. grid(64,4,4), block(256).
// =============================================================================
__global__ __launch_bounds__(256) void xT_kernel(const float* __restrict__ x)
{
    __shared__ float T[64][65];
    const int tid = threadIdx.x;
    const int n0 = blockIdx.x * 64, c0 = blockIdx.y * 64, b = blockIdx.z;

    {
        int cr = tid >> 2, q = tid & 3;
        const float4* src = (const float4*)(x + ((size_t)(b * C_ + c0 + cr)) * N_ + n0 + q * 16);
#pragma unroll
        for (int i = 0; i < 4; ++i) {
            float4 v = src[i];
            int nn = q * 16 + i * 4;
            T[cr][nn] = v.x; T[cr][nn + 1] = v.y; T[cr][nn + 2] = v.z; T[cr][nn + 3] = v.w;
        }
    }
    __syncthreads();

    u32* dst = (u32*)g_xT;
#pragma unroll
    for (int i = 0; i < 8; ++i) {
        int idx = tid * 8 + i;
        int n = idx >> 5, cp = idx & 31;
        u32 v = pack_bf16x2(T[2 * cp][n], T[2 * cp + 1][n]);
        dst[((size_t)(b * N_ + n0 + n)) * 128 + (c0 >> 1) + cp] = v;
    }
}

// =============================================================================
// Kernel 1: projection GEMM on tensor cores. Outputs fp16 Q/K/V.
// =============================================================================
#define WT_OFF 1024
#define XT_OFF 17408
#define SMEM_P 50176

__global__ __launch_bounds__(128, 4)
void proj_gemm()
{
    extern __shared__ char sm[];
    const u32 sb = smem_u32(sm);
    float* bs = (float*)sm;
    const int tid = threadIdx.x;
    const int w = tid >> 5, lane = tid & 31;
    const int gid = lane >> 2, qid = lane & 3;
    const int n0 = blockIdx.x * 128;
    const int z  = blockIdx.y;
    const int b  = blockIdx.z;
    const bool qk = (z == 0);
    const int jbase = qk ? 0 : z * 64;

    if (tid < 64) bs[tid] = g_bcat[jbase + tid];

    auto load_chunk = [&](int kc) {
        int buf = kc & 1;
#pragma unroll
        for (int i = 0; i < 4; ++i) {
            int idx = i * 128 + tid;
            int r = idx >> 3, q = idx & 7;
            cpa16(sb + WT_OFF + buf * 8192 + swz(r * 128 + q * 16),
                  g_wcat + (size_t)(jbase + r) * 256 + kc * 64 + q * 8);
        }
#pragma unroll
        for (int i = 0; i < 8; ++i) {
            int idx = i * 128 + tid;
            int r = idx >> 3, q = idx & 7;
            cpa16(sb + XT_OFF + buf * 16384 + swz(r * 128 + q * 16),
                  g_xT + ((size_t)(b * N_) + n0 + r) * 256 + kc * 64 + q * 8);
        }
    };

    load_chunk(0);
    CP_COMMIT;

    float D[2][8][4];
#pragma unroll
    for (int mt = 0; mt < 2; ++mt)
#pragma unroll
        for (int nt = 0; nt < 8; ++nt)
#pragma unroll
            for (int r = 0; r < 4; ++r) D[mt][nt][r] = 0.0f;

    for (int kc = 0; kc < 4; ++kc) {
        if (kc < 3) { load_chunk(kc + 1); CP_COMMIT; CP_WAIT1; }
        else        { CP_WAIT0; }
        __syncthreads();

        const u32 wbase = sb + WT_OFF + (kc & 1) * 8192;
        const u32 xbase = sb + XT_OFF + (kc & 1) * 16384;
        const u32 abase = qk ? xbase : wbase;
        const u32 bbase = qk ? wbase : xbase;
        const int arow  = qk ? w * 32 : (w & 1) * 32;
        const int brow  = qk ? 0 : (w >> 1) * 64;

#pragma unroll
        for (int ks = 0; ks < 4; ++ks) {
            u32 aA[2][4];
#pragma unroll
            for (int mt = 0; mt < 2; ++mt) {
                int row = arow + mt * 16 + (lane & 15);
                ldm_x4(abase + swz(row * 128 + (lane >> 4) * 16 + ks * 32),
                       aA[mt][0], aA[mt][1], aA[mt][2], aA[mt][3]);
            }
#pragma unroll
            for (int ntp = 0; ntp < 4; ++ntp) {
                u32 bB[4];
                int nrow = brow + ntp * 16 + (lane & 7) + ((lane >> 4) & 1) * 8;
                ldm_x4(bbase + swz(nrow * 128 + ((lane >> 3) & 1) * 16 + ks * 32),
                       bB[0], bB[1], bB[2], bB[3]);
                mma_bf16(D[0][2 * ntp],     aA[0], bB);
                mma_bf16(D[0][2 * ntp + 1], aA[0], bB + 2);
                mma_bf16(D[1][2 * ntp],     aA[1], bB);
                mma_bf16(D[1][2 * ntp + 1], aA[1], bB + 2);
            }
        }
        __syncthreads();
    }

    if (qk) {
#pragma unroll
        for (int mt = 0; mt < 2; ++mt) {
            int n = n0 + w * 32 + mt * 16 + gid;
#pragma unroll
            for (int nt = 0; nt < 8; ++nt) {
                int j = nt * 8 + 2 * qid;
                float b0 = bs[j], b1 = bs[j + 1];
                u32 lo = pack_f16x2(D[mt][nt][0] + b0, D[mt][nt][1] + b1);
                u32 hi = pack_f16x2(D[mt][nt][2] + b0, D[mt][nt][3] + b1);
                int jj = j < 32 ? j : j - 32;
                u32* dst = (u32*)(j < 32 ? g_q : g_k);
                dst[((size_t)(b * N_) + n) * 16 + (jj >> 1)]       = lo;
                dst[((size_t)(b * N_) + n + 8) * 16 + (jj >> 1)]   = hi;
            }
        }
    } else {
#pragma unroll
        for (int mt = 0; mt < 2; ++mt) {
            int chl = (w & 1) * 32 + mt * 16 + gid;
            int ch  = (z - 1) * 64 + chl;
            float bv0 = bs[chl], bv1 = bs[chl + 8];
#pragma unroll
            for (int nt = 0; nt < 8; ++nt) {
                int pix = (w >> 1) * 64 + nt * 8 + 2 * qid;
                u32 lo = pack_f16x2(D[mt][nt][0] + bv0, D[mt][nt][1] + bv0);
                u32 hi = pack_f16x2(D[mt][nt][2] + bv1, D[mt][nt][3] + bv1);
                u32* dst = (u32*)g_v;
                dst[((size_t)(b * C_ + ch)) * 2048 + ((n0 + pix) >> 1)]     = lo;
                dst[((size_t)(b * C_ + ch + 8)) * 2048 + ((n0 + pix) >> 1)] = hi;
            }
        }
    }
}

// =============================================================================
// Kernel 2: fp16 flash attention — 512 threads, BLOCK_M=128, 1 CTA/SM.
// EXACT R10 pipeline (best: 122.8us) with ONLY the addressing fixed:
// all smem access through u32 bases computed once per tile (no generic
// pointers / CVTA in the hot loops), P stores via st.shared.b32.
// SMEM: rowsum[128]f @0 | K 16KB @1024 | Q 3x8KB @17408 | P 2x16KB @41984 |
//       V 3x32KB @74752  => 173056 B
// =============================================================================
#define K_OFF     1024
#define Q_OFF     17408
#define P_OFF     41984
#define V_OFF     74752
#define SMEM_F    173056
#define STAGE_OFF 1024
#define NT        64

__device__ __forceinline__ void load_qv(u32 sb, int tid, int b, int t) {
    const int buf = t % 3;
    const int n0  = t * 64;
    if (tid < 256) {   // Q: 64 rows x 32 f16
        int row = tid >> 2, ch = tid & 3;
        cpa16(sb + Q_OFF + buf * 8192 + swz(row * 128 + ch * 16),
              g_q + (size_t)(b * N_ + n0 + row) * DQK_ + ch * 8);
    }
    // V: 256 channel rows x 64 f16 = 2048 cpa16 over 512 threads
    const __half* vbase = g_v + (size_t)b * C_ * N_ + n0;
#pragma unroll
    for (int r = 0; r < 4; ++r) {
        int idx = tid + 512 * r;
        int c = idx >> 3, ch = idx & 7;
        cpa16(sb + V_OFF + buf * 32768 + swz(c * 128 + ch * 16),
              vbase + (size_t)c * N_ + ch * 8);
    }
}

__global__ __launch_bounds__(512, 1)
void flash_mma(const float* __restrict__ x,
               const float* __restrict__ gamma,
               float* __restrict__ out)
{
    extern __shared__ char sm[];
    const u32 sb = smem_u32(sm);
    const int tid  = threadIdx.x;
    const int wid  = tid >> 5;
    const int lane = tid & 31;
    const int gid  = lane >> 2;
    const int qid  = lane & 3;
    const int b    = blockIdx.y;
    const int m0   = blockIdx.x * 128;

    if (tid < 128) ((float*)sm)[tid] = 0.0f;

    // prologue: K tile + tile 0
    {
        int row = tid >> 2, ch = tid & 3;
        cpa16(sb + K_OFF + swz(row * 128 + ch * 16),
              g_k + (size_t)(b * N_ + m0 + row) * DQK_ + ch * 8);
    }
    load_qv(sb, tid, b, 0);
    CP_COMMIT;
    CP_WAIT0;
    __syncthreads();

    // persistent K A-frags: rows (wid&7)*16 .. +15
    u32 aK[2][4];
    {
        int row = (wid & 7) * 16 + (lane & 15);
#pragma unroll
        for (int ks = 0; ks < 2; ++ks) {
            u32 addr = sb + K_OFF + swz(row * 128 + (lane >> 4) * 16 + ks * 32);
            ldm_x4(addr, aK[ks][0], aK[ks][1], aK[ks][2], aK[ks][3]);
        }
    }

    u32 D[2][8][2];                // fp16x2 accumulators
#pragma unroll
    for (int ms = 0; ms < 2; ++ms)
#pragma unroll
        for (int cg = 0; cg < 8; ++cg) { D[ms][cg][0] = 0u; D[ms][cg][1] = 0u; }
    float rs0 = 0.0f, rs1 = 0.0f;

    const int rg  = wid & 7;   // S row group
    const int csh = wid >> 3;  // S col half
    const int pr  = wid & 3;   // PV row group
    const int pc  = wid >> 2;  // PV channel group

    for (int t = 0; t < NT; ++t) {
        CP_WAIT0;                  // QV(t) arrived (committed one full tile ago)
        __syncthreads();           // QV(t) + P(t-1) visible to all warps

        // ---- prefetch tile t+1 (clamped; tail reload is idempotent) ----
        {
            int tn = (t + 1 < NT) ? t + 1 : NT - 1;
            load_qv(sb, tid, b, tn);
            CP_COMMIT;
        }

        // ---- S(t) = K . Q(t)^T  (issued FIRST -> completes first in-order) ----
        const u32 qb = sb + Q_OFF + (u32)((t % 3) * 8192);
        float S[4][4];
#pragma unroll
        for (int ns = 0; ns < 4; ++ns)
#pragma unroll
            for (int r = 0; r < 4; ++r) S[ns][r] = 0.0f;

        u32 bQ[2][2][4];
#pragma unroll
        for (int nn = 0; nn < 2; ++nn) {
            int nrow = csh * 32 + nn * 16 + (lane & 7) + ((lane >> 4) & 1) * 8;
#pragma unroll
            for (int ks = 0; ks < 2; ++ks) {
                u32 addr = qb + swz((u32)(nrow * 128 + ((lane >> 3) & 1) * 16 + ks * 32));
                ldm_x4(addr, bQ[ks][nn][0], bQ[ks][nn][1], bQ[ks][nn][2], bQ[ks][nn][3]);
            }
        }
#pragma unroll
        for (int ns = 0; ns < 4; ++ns)
#pragma unroll
            for (int ks = 0; ks < 2; ++ks)
                mma_f16_f32(S[ns], aK[ks], &bQ[ks][ns >> 1][(ns & 1) * 2]);

        // ---- PV(t-1): D += P(t-1) . V(t-1)  (u32 bases, no CVTA) ----
        if (t > 0) {
            const u32 pb = sb + P_OFF + (u32)(((t - 1) & 1) * 16384);
            const u32 vb = sb + V_OFF + (u32)(((t - 1) % 3) * 32768);
#pragma unroll
            for (int ksn = 0; ksn < 4; ++ksn) {
                u32 aP[2][4];
#pragma unroll
                for (int ms = 0; ms < 2; ++ms) {
                    int row = pr * 32 + ms * 16 + (lane & 15);
                    ldm_x4(pb + swz((u32)(row * 128 + (lane >> 4) * 16 + ksn * 32)),
                           aP[ms][0], aP[ms][1], aP[ms][2], aP[ms][3]);
                }
                u32 bV[4][4];
#pragma unroll
                for (int pp = 0; pp < 4; ++pp) {
                    int crow = pc * 64 + pp * 16 + (lane & 7) + ((lane >> 4) & 1) * 8;
                    ldm_x4(vb + swz((u32)(crow * 128 + ((lane >> 3) & 1) * 16 + ksn * 32)),
                           bV[pp][0], bV[pp][1], bV[pp][2], bV[pp][3]);
                }
#pragma unroll
                for (int ms = 0; ms < 2; ++ms)
#pragma unroll
                    for (int cg = 0; cg < 8; ++cg)
                        mma_f16(D[ms][cg], aP[ms], &bV[cg >> 1][(cg & 1) * 2]);
            }
        }

        // ---- exp(t) in f16x2 -> P[t&1] via sts32; rowsums -> f32 ----
        {
            const int mlo = rg * 16 + gid;
            const u32 pw = sb + P_OFF + (u32)((t & 1) * 16384);
            u32 rsa = 0u, rsb = 0u;
#pragma unroll
            for (int ns = 0; ns < 4; ++ns) {
                u32 p0 = pack_f16x2(S[ns][0], S[ns][1]);
                u32 p1 = pack_f16x2(S[ns][2], S[ns][3]);
                asm("ex2.approx.f16x2 %0, %0;" : "+r"(p0));
                asm("ex2.approx.f16x2 %0, %0;" : "+r"(p1));
                asm("add.rn.f16x2 %0, %0, %1;" : "+r"(rsa) : "r"(p0));
                asm("add.rn.f16x2 %0, %0, %1;" : "+r"(rsb) : "r"(p1));
                int n = csh * 32 + ns * 8 + 2 * qid;
                sts32(pw + swz((u32)(mlo * 128 + n * 2)), p0);
                sts32(pw + swz((u32)((mlo + 8) * 128 + n * 2)), p1);
            }
            float2 fa = __half22float2(*(__half2*)&rsa);
            float2 fb = __half22float2(*(__half2*)&rsb);
            rs0 += fa.x + fa.y;
            rs1 += fb.x + fb.y;
        }
    }

    // ---- epilogue PV(NT-1) ----
    CP_WAIT0;
    __syncthreads();               // P(NT-1) visible
    {
        const u32 pb = sb + P_OFF + (u32)(((NT - 1) & 1) * 16384);
        const u32 vb = sb + V_OFF + (u32)(((NT - 1) % 3) * 32768);
#pragma unroll
        for (int ksn = 0; ksn < 4; ++ksn) {
            u32 aP[2][4];
#pragma unroll
            for (int ms = 0; ms < 2; ++ms) {
                int row = pr * 32 + ms * 16 + (lane & 15);
                ldm_x4(pb + swz((u32)(row * 128 + (lane >> 4) * 16 + ksn * 32)),
                       aP[ms][0], aP[ms][1], aP[ms][2], aP[ms][3]);
            }
            u32 bV[4][4];
#pragma unroll
            for (int pp = 0; pp < 4; ++pp) {
                int crow = pc * 64 + pp * 16 + (lane & 7) + ((lane >> 4) & 1) * 8;
                ldm_x4(vb + swz((u32)(crow * 128 + ((lane >> 3) & 1) * 16 + ksn * 32)),
                       bV[pp][0], bV[pp][1], bV[pp][2], bV[pp][3]);
            }
#pragma unroll
            for (int ms = 0; ms < 2; ++ms)
#pragma unroll
                for (int cg = 0; cg < 8; ++cg)
                    mma_f16(D[ms][cg], aP[ms], &bV[cg >> 1][(cg & 1) * 2]);
        }
    }

    // ---- row sums: 4-lane reduce + cross-warp atomic ----
    __syncthreads();
    rs0 += __shfl_xor_sync(0xffffffffu, rs0, 1);
    rs0 += __shfl_xor_sync(0xffffffffu, rs0, 2);
    rs1 += __shfl_xor_sync(0xffffffffu, rs1, 1);
    rs1 += __shfl_xor_sync(0xffffffffu, rs1, 2);
    if (qid == 0) {
        atomicAdd(&((float*)sm)[rg * 16 + gid],     rs0);
        atomicAdd(&((float*)sm)[rg * 16 + gid + 8], rs1);
    }
    __syncthreads();

    // ---- epilogue in two 64-row passes: stage [256 ch][64 m], coalesced out ----
    float* stage = (float*)(sm + STAGE_OFF);   // [256][66]
    const float g = gamma[0];
#pragma unroll
    for (int h = 0; h < 2; ++h) {
        if ((pr >> 1) == h) {
#pragma unroll
            for (int ms = 0; ms < 2; ++ms) {
                int r0 = pr * 32 + ms * 16 + gid;
                int r1 = r0 + 8;
                float i0 = 1.0f / ((float*)sm)[r0];
                float i1 = 1.0f / ((float*)sm)[r1];
                int l0 = r0 - h * 64, l1 = r1 - h * 64;
#pragma unroll
                for (int cg = 0; cg < 8; ++cg) {
                    int c = pc * 64 + cg * 8 + 2 * qid;
                    float2 flo = __half22float2(*reinterpret_cast<__half2*>(&D[ms][cg][0]));
                    float2 fhi = __half22float2(*reinterpret_cast<__half2*>(&D[ms][cg][1]));
                    stage[c * 66 + l0]       = flo.x * i0;
                    stage[(c + 1) * 66 + l0] = flo.y * i0;
                    stage[c * 66 + l1]       = fhi.x * i1;
                    stage[(c + 1) * 66 + l1] = fhi.y * i1;
                }
            }
        }
        __syncthreads();

#pragma unroll 4
        for (int i = 0; i < 32; ++i) {
            int m = tid & 63;
            int c = (tid >> 6) + 8 * i;
            size_t ga = ((size_t)(b * C_ + c)) * N_ + m0 + h * 64 + m;
            out[ga] = g * stage[c * 66 + m] + x[ga];
        }
        __syncthreads();
    }
}

// =============================================================================
// launcher
// =============================================================================
extern "C" void kernel_launch(void* const* d_in, const int* in_sizes, int n_in,
                              void* d_out, int out_size)
{
    const float* x     = (const float*)d_in[0];
    const float* Wq    = (const float*)d_in[1];
    const float* bq    = (const float*)d_in[2];
    const float* Wk    = (const float*)d_in[3];
    const float* bk    = (const float*)d_in[4];
    const float* Wv    = (const float*)d_in[5];
    const float* bv    = (const float*)d_in[6];
    const float* gamma = (const float*)d_in[7];
    float* out = (float*)d_out;

    (void)cudaFuncSetAttribute(proj_gemm,
                               cudaFuncAttributeMaxDynamicSharedMemorySize, SMEM_P);
    (void)cudaFuncSetAttribute(flash_mma,
                               cudaFuncAttributeMaxDynamicSharedMemorySize, SMEM_F);

    wconv<<<320, 256>>>(Wq, bq, Wk, bk, Wv, bv);
    xT_kernel<<<dim3(N_ / 64, C_ / 64, B_), 256>>>(x);
    proj_gemm<<<dim3(N_ / 128, 5, B_), 128, SMEM_P>>>();
    flash_mma<<<dim3(N_ / 128, B_), 512, SMEM_F>>>(x, gamma, out);
}

// round 15
// speedup vs baseline: 1.0620x; 1.0319x over previous
#include <cuda_runtime.h>
#include <cuda_bf16.h>
#include <cuda_fp16.h>
#include <cstdint>

// Problem constants
#define B_   4
#define C_   256
#define DQK_ 32
#define N_   4096   // 64*64

typedef uint32_t u32;

// ---------------- scratch (no allocation allowed -> device globals) ----------
__device__ __half        g_q[(size_t)B_ * N_ * DQK_];   // [B][N][32], Q pre-scaled by log2(e)
__device__ __half        g_k[(size_t)B_ * N_ * DQK_];   // [B][N][32]
__device__ __half        g_v[(size_t)B_ * C_ * N_];     // [B][C][N] channel-major
__device__ __nv_bfloat16 g_xT[(size_t)B_ * N_ * C_];    // [B][N][C]  x transposed, bf16
__device__ __nv_bfloat16 g_wcat[320 * 256];             // [Wq*log2e; Wk; Wv]
__device__ float         g_bcat[320];                   // [bq*log2e; bk; bv]

// ---------------- helpers ------------------------------------------------------
__device__ __forceinline__ u32 pack_bf16x2(float lo, float hi) {
    u32 d;
    asm("cvt.rn.bf16x2.f32 %0, %1, %2;" : "=r"(d) : "f"(hi), "f"(lo));
    return d;
}
__device__ __forceinline__ u32 pack_f16x2(float lo, float hi) {
    u32 d;
    asm("cvt.rn.f16x2.f32 %0, %1, %2;" : "=r"(d) : "f"(hi), "f"(lo));
    return d;
}
__device__ __forceinline__ u32 smem_u32(const void* p) {
    u32 a;
    asm("{ .reg .u64 t; cvta.to.shared.u64 t, %1; cvt.u32.u64 %0, t; }" : "=r"(a) : "l"(p));
    return a;
}
__device__ __forceinline__ void ldm_x4(u32 addr, u32& r0, u32& r1, u32& r2, u32& r3) {
    asm volatile("ldmatrix.sync.aligned.m8n8.x4.shared.b16 {%0,%1,%2,%3}, [%4];"
                 : "=r"(r0), "=r"(r1), "=r"(r2), "=r"(r3) : "r"(addr));
}
// bf16 inputs, f32 accum (projection GEMM)
__device__ __forceinline__ void mma_bf16(float* d, const u32* a, const u32* b) {
    asm volatile(
        "mma.sync.aligned.m16n8k16.row.col.f32.bf16.bf16.f32 "
        "{%0,%1,%2,%3},{%4,%5,%6,%7},{%8,%9},{%0,%1,%2,%3};"
        : "+f"(d[0]), "+f"(d[1]), "+f"(d[2]), "+f"(d[3])
        : "r"(a[0]), "r"(a[1]), "r"(a[2]), "r"(a[3]), "r"(b[0]), "r"(b[1]));
}
// fp16 inputs, f32 accum (S = K.Q^T)
__device__ __forceinline__ void mma_f16_f32(float* d, const u32* a, const u32* b) {
    asm volatile(
        "mma.sync.aligned.m16n8k16.row.col.f32.f16.f16.f32 "
        "{%0,%1,%2,%3},{%4,%5,%6,%7},{%8,%9},{%0,%1,%2,%3};"
        : "+f"(d[0]), "+f"(d[1]), "+f"(d[2]), "+f"(d[3])
        : "r"(a[0]), "r"(a[1]), "r"(a[2]), "r"(a[3]), "r"(b[0]), "r"(b[1]));
}
// fp16 inputs, fp16 accum (PV) — D is 2 regs (4 halves)
__device__ __forceinline__ void mma_f16(u32* d, const u32* a, const u32* b) {
    asm volatile(
        "mma.sync.aligned.m16n8k16.row.col.f16.f16.f16.f16 "
        "{%0,%1},{%2,%3,%4,%5},{%6,%7},{%0,%1};"
        : "+r"(d[0]), "+r"(d[1])
        : "r"(a[0]), "r"(a[1]), "r"(a[2]), "r"(a[3]), "r"(b[0]), "r"(b[1]));
}
__device__ __forceinline__ void cpa16(u32 dst, const void* src) {
    asm volatile("cp.async.cg.shared.global [%0], [%1], 16;" :: "r"(dst), "l"(src));
}
#define CP_COMMIT  asm volatile("cp.async.commit_group;")
#define CP_WAIT0   asm volatile("cp.async.wait_group 0;")
#define CP_WAIT1   asm volatile("cp.async.wait_group 1;")

__device__ __forceinline__ u32 swz(u32 off) { return off ^ ((off >> 3) & 0x70); }

#define L2E 1.44269504088896f

// =============================================================================
// Kernel 0: FUSED weight-convert + x-transpose. grid(1344), block(256).
//   blocks [0,1024): xT tiles  (decode n0/c0/b from blockIdx.x)
//   blocks [1024,1344): wconv row j = blockIdx.x - 1024
// =============================================================================
__global__ __launch_bounds__(256) void wxT_kernel(
    const float* __restrict__ x,
    const float* __restrict__ Wq, const float* __restrict__ bq,
    const float* __restrict__ Wk, const float* __restrict__ bk,
    const float* __restrict__ Wv, const float* __restrict__ bv)
{
    const int bx  = blockIdx.x;
    const int tid = threadIdx.x;

    if (bx >= 1024) {
        // ---- wconv: one j row per block ----
        int j = bx - 1024, c = tid;
        const float* src;
        float s = 1.0f, bias;
        if (j < 32)       { src = Wq + j * 256;        s = L2E; bias = bq[j] * L2E; }
        else if (j < 64)  { src = Wk + (j - 32) * 256;          bias = bk[j - 32];  }
        else              { src = Wv + (j - 64) * 256;          bias = bv[j - 64];  }
        g_wcat[j * 256 + c] = __float2bfloat16(src[c] * s);
        if (c == 0) g_bcat[j] = bias;
        return;
    }

    // ---- xT: 64x64 tile transpose+convert ----
    __shared__ float T[64][65];
    const int n0 = (bx & 63) * 64;
    const int c0 = ((bx >> 6) & 3) * 64;
    const int b  = bx >> 8;

    {
        int cr = tid >> 2, q = tid & 3;
        const float4* src = (const float4*)(x + ((size_t)(b * C_ + c0 + cr)) * N_ + n0 + q * 16);
#pragma unroll
        for (int i = 0; i < 4; ++i) {
            float4 v = src[i];
            int nn = q * 16 + i * 4;
            T[cr][nn] = v.x; T[cr][nn + 1] = v.y; T[cr][nn + 2] = v.z; T[cr][nn + 3] = v.w;
        }
    }
    __syncthreads();

    u32* dst = (u32*)g_xT;
#pragma unroll
    for (int i = 0; i < 8; ++i) {
        int idx = tid * 8 + i;
        int n = idx >> 5, cp = idx & 31;
        u32 v = pack_bf16x2(T[2 * cp][n], T[2 * cp + 1][n]);
        dst[((size_t)(b * N_ + n0 + n)) * 128 + (c0 >> 1) + cp] = v;
    }
}

// =============================================================================
// Kernel 1: projection GEMM on tensor cores. Outputs fp16 Q/K/V. (unchanged)
// =============================================================================
#define WT_OFF 1024
#define XT_OFF 17408
#define SMEM_P 50176

__global__ __launch_bounds__(128, 4)
void proj_gemm()
{
    extern __shared__ char sm[];
    const u32 sb = smem_u32(sm);
    float* bs = (float*)sm;
    const int tid = threadIdx.x;
    const int w = tid >> 5, lane = tid & 31;
    const int gid = lane >> 2, qid = lane & 3;
    const int n0 = blockIdx.x * 128;
    const int z  = blockIdx.y;
    const int b  = blockIdx.z;
    const bool qk = (z == 0);
    const int jbase = qk ? 0 : z * 64;

    if (tid < 64) bs[tid] = g_bcat[jbase + tid];

    auto load_chunk = [&](int kc) {
        int buf = kc & 1;
#pragma unroll
        for (int i = 0; i < 4; ++i) {
            int idx = i * 128 + tid;
            int r = idx >> 3, q = idx & 7;
            cpa16(sb + WT_OFF + buf * 8192 + swz(r * 128 + q * 16),
                  g_wcat + (size_t)(jbase + r) * 256 + kc * 64 + q * 8);
        }
#pragma unroll
        for (int i = 0; i < 8; ++i) {
            int idx = i * 128 + tid;
            int r = idx >> 3, q = idx & 7;
            cpa16(sb + XT_OFF + buf * 16384 + swz(r * 128 + q * 16),
                  g_xT + ((size_t)(b * N_) + n0 + r) * 256 + kc * 64 + q * 8);
        }
    };

    load_chunk(0);
    CP_COMMIT;

    float D[2][8][4];
#pragma unroll
    for (int mt = 0; mt < 2; ++mt)
#pragma unroll
        for (int nt = 0; nt < 8; ++nt)
#pragma unroll
            for (int r = 0; r < 4; ++r) D[mt][nt][r] = 0.0f;

    for (int kc = 0; kc < 4; ++kc) {
        if (kc < 3) { load_chunk(kc + 1); CP_COMMIT; CP_WAIT1; }
        else        { CP_WAIT0; }
        __syncthreads();

        const u32 wbase = sb + WT_OFF + (kc & 1) * 8192;
        const u32 xbase = sb + XT_OFF + (kc & 1) * 16384;
        const u32 abase = qk ? xbase : wbase;
        const u32 bbase = qk ? wbase : xbase;
        const int arow  = qk ? w * 32 : (w & 1) * 32;
        const int brow  = qk ? 0 : (w >> 1) * 64;

#pragma unroll
        for (int ks = 0; ks < 4; ++ks) {
            u32 aA[2][4];
#pragma unroll
            for (int mt = 0; mt < 2; ++mt) {
                int row = arow + mt * 16 + (lane & 15);
                ldm_x4(abase + swz(row * 128 + (lane >> 4) * 16 + ks * 32),
                       aA[mt][0], aA[mt][1], aA[mt][2], aA[mt][3]);
            }
#pragma unroll
            for (int ntp = 0; ntp < 4; ++ntp) {
                u32 bB[4];
                int nrow = brow + ntp * 16 + (lane & 7) + ((lane >> 4) & 1) * 8;
                ldm_x4(bbase + swz(nrow * 128 + ((lane >> 3) & 1) * 16 + ks * 32),
                       bB[0], bB[1], bB[2], bB[3]);
                mma_bf16(D[0][2 * ntp],     aA[0], bB);
                mma_bf16(D[0][2 * ntp + 1], aA[0], bB + 2);
                mma_bf16(D[1][2 * ntp],     aA[1], bB);
                mma_bf16(D[1][2 * ntp + 1], aA[1], bB + 2);
            }
        }
        __syncthreads();
    }

    if (qk) {
#pragma unroll
        for (int mt = 0; mt < 2; ++mt) {
            int n = n0 + w * 32 + mt * 16 + gid;
#pragma unroll
            for (int nt = 0; nt < 8; ++nt) {
                int j = nt * 8 + 2 * qid;
                float b0 = bs[j], b1 = bs[j + 1];
                u32 lo = pack_f16x2(D[mt][nt][0] + b0, D[mt][nt][1] + b1);
                u32 hi = pack_f16x2(D[mt][nt][2] + b0, D[mt][nt][3] + b1);
                int jj = j < 32 ? j : j - 32;
                u32* dst = (u32*)(j < 32 ? g_q : g_k);
                dst[((size_t)(b * N_) + n) * 16 + (jj >> 1)]       = lo;
                dst[((size_t)(b * N_) + n + 8) * 16 + (jj >> 1)]   = hi;
            }
        }
    } else {
#pragma unroll
        for (int mt = 0; mt < 2; ++mt) {
            int chl = (w & 1) * 32 + mt * 16 + gid;
            int ch  = (z - 1) * 64 + chl;
            float bv0 = bs[chl], bv1 = bs[chl + 8];
#pragma unroll
            for (int nt = 0; nt < 8; ++nt) {
                int pix = (w >> 1) * 64 + nt * 8 + 2 * qid;
                u32 lo = pack_f16x2(D[mt][nt][0] + bv0, D[mt][nt][1] + bv0);
                u32 hi = pack_f16x2(D[mt][nt][2] + bv1, D[mt][nt][3] + bv1);
                u32* dst = (u32*)g_v;
                dst[((size_t)(b * C_ + ch)) * 2048 + ((n0 + pix) >> 1)]     = lo;
                dst[((size_t)(b * C_ + ch + 8)) * 2048 + ((n0 + pix) >> 1)] = hi;
            }
        }
    }
}

// =============================================================================
// Kernel 2: fp16 flash attention — R10 VERBATIM (best measured: 122.8us).
// 512 threads, BLOCK_M=128, 1 CTA/SM. ONE __syncthreads per tile.
// V/Q triple-buffered, P double-buffered.
// SMEM: rowsum[128]f @0 | K 16KB @1024 | Q 3x8KB @17408 | P 2x16KB @41984 |
//       V 3x32KB @74752  => 173056 B
// =============================================================================
#define K_OFF     1024
#define Q_OFF     17408
#define P_OFF     41984
#define V_OFF     74752
#define SMEM_F    173056
#define STAGE_OFF 1024
#define NT        64

__device__ __forceinline__ void load_qv(u32 sb, int tid, int b, int t) {
    const int buf = t % 3;
    const int n0  = t * 64;
    if (tid < 256) {   // Q: 64 rows x 32 f16
        int row = tid >> 2, ch = tid & 3;
        cpa16(sb + Q_OFF + buf * 8192 + swz(row * 128 + ch * 16),
              g_q + (size_t)(b * N_ + n0 + row) * DQK_ + ch * 8);
    }
    // V: 256 channel rows x 64 f16 = 2048 cpa16 over 512 threads
    const __half* vbase = g_v + (size_t)b * C_ * N_ + n0;
#pragma unroll
    for (int r = 0; r < 4; ++r) {
        int idx = tid + 512 * r;
        int c = idx >> 3, ch = idx & 7;
        cpa16(sb + V_OFF + buf * 32768 + swz(c * 128 + ch * 16),
              vbase + (size_t)c * N_ + ch * 8);
    }
}

__global__ __launch_bounds__(512, 1)
void flash_mma(const float* __restrict__ x,
               const float* __restrict__ gamma,
               float* __restrict__ out)
{
    extern __shared__ char sm[];
    const u32 sb = smem_u32(sm);
    const int tid  = threadIdx.x;
    const int wid  = tid >> 5;
    const int lane = tid & 31;
    const int gid  = lane >> 2;
    const int qid  = lane & 3;
    const int b    = blockIdx.y;
    const int m0   = blockIdx.x * 128;

    if (tid < 128) ((float*)sm)[tid] = 0.0f;

    // prologue: K tile + tile 0
    {
        int row = tid >> 2, ch = tid & 3;
        cpa16(sb + K_OFF + swz(row * 128 + ch * 16),
              g_k + (size_t)(b * N_ + m0 + row) * DQK_ + ch * 8);
    }
    load_qv(sb, tid, b, 0);
    CP_COMMIT;
    CP_WAIT0;
    __syncthreads();

    // persistent K A-frags: rows (wid&7)*16 .. +15
    u32 aK[2][4];
    {
        int row = (wid & 7) * 16 + (lane & 15);
#pragma unroll
        for (int ks = 0; ks < 2; ++ks) {
            u32 addr = sb + K_OFF + swz(row * 128 + (lane >> 4) * 16 + ks * 32);
            ldm_x4(addr, aK[ks][0], aK[ks][1], aK[ks][2], aK[ks][3]);
        }
    }

    u32 D[2][8][2];                // fp16x2 accumulators
#pragma unroll
    for (int ms = 0; ms < 2; ++ms)
#pragma unroll
        for (int cg = 0; cg < 8; ++cg) { D[ms][cg][0] = 0u; D[ms][cg][1] = 0u; }
    float rs0 = 0.0f, rs1 = 0.0f;

    const int rg  = wid & 7;   // S row group
    const int csh = wid >> 3;  // S col half
    const int pr  = wid & 3;   // PV row group
    const int pc  = wid >> 2;  // PV channel group

    for (int t = 0; t < NT; ++t) {
        CP_WAIT0;                  // QV(t) arrived (committed one full tile ago)
        __syncthreads();           // QV(t) + P(t-1) visible to all warps

        // ---- prefetch tile t+1 ----
        if (t + 1 < NT) {
            load_qv(sb, tid, b, t + 1);
            CP_COMMIT;
        }

        // ---- S(t) = K . Q(t)^T  (issued FIRST -> completes first in-order) ----
        const u32 qb = sb + Q_OFF + (t % 3) * 8192;
        float S[4][4];
#pragma unroll
        for (int ns = 0; ns < 4; ++ns)
#pragma unroll
            for (int r = 0; r < 4; ++r) S[ns][r] = 0.0f;

        u32 bQ[2][2][4];
#pragma unroll
        for (int nn = 0; nn < 2; ++nn) {
            int nrow = csh * 32 + nn * 16 + (lane & 7) + ((lane >> 4) & 1) * 8;
#pragma unroll
            for (int ks = 0; ks < 2; ++ks) {
                u32 addr = qb + swz(nrow * 128 + ((lane >> 3) & 1) * 16 + ks * 32);
                ldm_x4(addr, bQ[ks][nn][0], bQ[ks][nn][1], bQ[ks][nn][2], bQ[ks][nn][3]);
            }
        }
#pragma unroll
        for (int ns = 0; ns < 4; ++ns)
#pragma unroll
            for (int ks = 0; ks < 2; ++ks)
                mma_f16_f32(S[ns], aK[ks], &bQ[ks][ns >> 1][(ns & 1) * 2]);

        // ---- PV(t-1): D += P(t-1) . V(t-1)  (drains while exp runs) ----
        if (t > 0) {
            char* pb = sm + P_OFF + ((t - 1) & 1) * 16384;
            char* vb = sm + V_OFF + ((t - 1) % 3) * 32768;
#pragma unroll
            for (int ksn = 0; ksn < 4; ++ksn) {
                u32 aP[2][4];
#pragma unroll
                for (int ms = 0; ms < 2; ++ms) {
                    int row = pr * 32 + ms * 16 + (lane & 15);
                    u32 addr = smem_u32(pb) + swz(row * 128 + (lane >> 4) * 16 + ksn * 32);
                    ldm_x4(addr, aP[ms][0], aP[ms][1], aP[ms][2], aP[ms][3]);
                }
                u32 bV[4][4];
#pragma unroll
                for (int pp = 0; pp < 4; ++pp) {
                    int crow = pc * 64 + pp * 16 + (lane & 7) + ((lane >> 4) & 1) * 8;
                    u32 addr = smem_u32(vb) + swz(crow * 128 + ((lane >> 3) & 1) * 16 + ksn * 32);
                    ldm_x4(addr, bV[pp][0], bV[pp][1], bV[pp][2], bV[pp][3]);
                }
#pragma unroll
                for (int ms = 0; ms < 2; ++ms)
#pragma unroll
                    for (int cg = 0; cg < 8; ++cg)
                        mma_f16(D[ms][cg], aP[ms], &bV[cg >> 1][(cg & 1) * 2]);
            }
        }

        // ---- exp(t) in f16x2 -> P[t&1]; rowsums via HADD2, flushed to f32 ----
        {
            const int mlo = rg * 16 + gid;
            char* pw = sm + P_OFF + (t & 1) * 16384;
            u32 rsa = 0u, rsb = 0u;
#pragma unroll
            for (int ns = 0; ns < 4; ++ns) {
                u32 p0 = pack_f16x2(S[ns][0], S[ns][1]);
                u32 p1 = pack_f16x2(S[ns][2], S[ns][3]);
                asm("ex2.approx.f16x2 %0, %0;" : "+r"(p0));
                asm("ex2.approx.f16x2 %0, %0;" : "+r"(p1));
                asm("add.rn.f16x2 %0, %0, %1;" : "+r"(rsa) : "r"(p0));
                asm("add.rn.f16x2 %0, %0, %1;" : "+r"(rsb) : "r"(p1));
                int n = csh * 32 + ns * 8 + 2 * qid;
                *(u32*)(pw - sb + (size_t)sm + swz(mlo * 128 + n * 2))       = p0;
                *(u32*)(pw - sb + (size_t)sm + swz((mlo + 8) * 128 + n * 2)) = p1;
            }
            float2 fa = __half22float2(*(__half2*)&rsa);
            float2 fb = __half22float2(*(__half2*)&rsb);
            rs0 += fa.x + fa.y;
            rs1 += fb.x + fb.y;
        }
    }

    // ---- epilogue PV(NT-1) ----
    CP_WAIT0;
    __syncthreads();               // P(NT-1) visible
    {
        char* pb = sm + P_OFF + ((NT - 1) & 1) * 16384;
        char* vb = sm + V_OFF + ((NT - 1) % 3) * 32768;
#pragma unroll
        for (int ksn = 0; ksn < 4; ++ksn) {
            u32 aP[2][4];
#pragma unroll
            for (int ms = 0; ms < 2; ++ms) {
                int row = pr * 32 + ms * 16 + (lane & 15);
                u32 addr = smem_u32(pb) + swz(row * 128 + (lane >> 4) * 16 + ksn * 32);
                ldm_x4(addr, aP[ms][0], aP[ms][1], aP[ms][2], aP[ms][3]);
            }
            u32 bV[4][4];
#pragma unroll
            for (int pp = 0; pp < 4; ++pp) {
                int crow = pc * 64 + pp * 16 + (lane & 7) + ((lane >> 4) & 1) * 8;
                u32 addr = smem_u32(vb) + swz(crow * 128 + ((lane >> 3) & 1) * 16 + ksn * 32);
                ldm_x4(addr, bV[pp][0], bV[pp][1], bV[pp][2], bV[pp][3]);
            }
#pragma unroll
            for (int ms = 0; ms < 2; ++ms)
#pragma unroll
                for (int cg = 0; cg < 8; ++cg)
                    mma_f16(D[ms][cg], aP[ms], &bV[cg >> 1][(cg & 1) * 2]);
        }
    }

    // ---- row sums: 4-lane reduce + cross-warp atomic ----
    __syncthreads();
    rs0 += __shfl_xor_sync(0xffffffffu, rs0, 1);
    rs0 += __shfl_xor_sync(0xffffffffu, rs0, 2);
    rs1 += __shfl_xor_sync(0xffffffffu, rs1, 1);
    rs1 += __shfl_xor_sync(0xffffffffu, rs1, 2);
    if (qid == 0) {
        atomicAdd(&((float*)sm)[rg * 16 + gid],     rs0);
        atomicAdd(&((float*)sm)[rg * 16 + gid + 8], rs1);
    }
    __syncthreads();

    // ---- epilogue in two 64-row passes: stage [256 ch][64 m], coalesced out ----
    float* stage = (float*)(sm + STAGE_OFF);   // [256][66]
    const float g = gamma[0];
#pragma unroll
    for (int h = 0; h < 2; ++h) {
        if ((pr >> 1) == h) {
#pragma unroll
            for (int ms = 0; ms < 2; ++ms) {
                int r0 = pr * 32 + ms * 16 + gid;
                int r1 = r0 + 8;
                float i0 = 1.0f / ((float*)sm)[r0];
                float i1 = 1.0f / ((float*)sm)[r1];
                int l0 = r0 - h * 64, l1 = r1 - h * 64;
#pragma unroll
                for (int cg = 0; cg < 8; ++cg) {
                    int c = pc * 64 + cg * 8 + 2 * qid;
                    float2 flo = __half22float2(*reinterpret_cast<__half2*>(&D[ms][cg][0]));
                    float2 fhi = __half22float2(*reinterpret_cast<__half2*>(&D[ms][cg][1]));
                    stage[c * 66 + l0]       = flo.x * i0;
                    stage[(c + 1) * 66 + l0] = flo.y * i0;
                    stage[c * 66 + l1]       = fhi.x * i1;
                    stage[(c + 1) * 66 + l1] = fhi.y * i1;
                }
            }
        }
        __syncthreads();

#pragma unroll 4
        for (int i = 0; i < 32; ++i) {
            int m = tid & 63;
            int c = (tid >> 6) + 8 * i;
            size_t ga = ((size_t)(b * C_ + c)) * N_ + m0 + h * 64 + m;
            out[ga] = g * stage[c * 66 + m] + x[ga];
        }
        __syncthreads();
    }
}

// =============================================================================
// launcher
// =============================================================================
extern "C" void kernel_launch(void* const* d_in, const int* in_sizes, int n_in,
                              void* d_out, int out_size)
{
    const float* x     = (const float*)d_in[0];
    const float* Wq    = (const float*)d_in[1];
    const float* bq    = (const float*)d_in[2];
    const float* Wk    = (const float*)d_in[3];
    const float* bk    = (const float*)d_in[4];
    const float* Wv    = (const float*)d_in[5];
    const float* bv    = (const float*)d_in[6];
    const float* gamma = (const float*)d_in[7];
    float* out = (float*)d_out;

    (void)cudaFuncSetAttribute(proj_gemm,
                               cudaFuncAttributeMaxDynamicSharedMemorySize, SMEM_P);
    (void)cudaFuncSetAttribute(flash_mma,
                               cudaFuncAttributeMaxDynamicSharedMemorySize, SMEM_F);

    wxT_kernel<<<1344, 256>>>(x, Wq, bq, Wk, bk, Wv, bv);
    proj_gemm<<<dim3(N_ / 128, 5, B_), 128, SMEM_P>>>();
    flash_mma<<<dim3(N_ / 128, B_), 512, SMEM_F>>>(x, gamma, out);
}